// round 15
// baseline (speedup 1.0000x reference)
#include <cuda_runtime.h>
#include <cuda_bf16.h>
#include <cstdint>

// Problem constants
#define BSZ   256
#define LSEQ  65536
#define HIST  256
#define WINW  64
#define DIMC  256
#define NPAT  64
#define TSTEP 1024

// Fused tiling: 16 tiles of 64 t-steps per batch
#define TT    64
#define NTIL  (TSTEP / TT)           // 16
#define XWP   (((TT-1)*WINW + HIST) / 2)   // 2144 bf16x2 pairs
#define SOUTP 132                    // souts row stride (uints)

// smem layout (bytes)
#define FB_BIAS  0                   // 256 f = 1024
#define FB_SXP   1024                // 2176 u = 8704
#define FB_SOUT  9728                // 64*132 u = 33792
#define FB_SRING 43520               // 2*64*64 f = 32768
#define FB_ERING 76288               // 2*64*64 f = 32768
#define FB_SINV  109056              // 2*64 f = 512
#define FUSED_SMEM 109568

// Prepped weights
__device__ uint32_t g_wP[(HIST/2) * DIMC];      // W^T bf16x2 [k2][n]
__device__ uint32_t g_keysP[(DIMC/2) * NPAT];   // keys bf16x2 [d2][p]

// ---------------------------------------------------------------------------
__device__ __forceinline__ uint32_t pack_bf16(float lo, float hi) {
    uint32_t r;
    asm("cvt.rn.bf16x2.f32 %0, %1, %2;" : "=r"(r) : "f"(hi), "f"(lo));
    return r;
}

// D += A(16x16 bf16, row) * B(16x8 bf16, col), fp32 accum
__device__ __forceinline__ void mma16(float c[4], const uint32_t a[4],
                                      uint32_t b0, uint32_t b1) {
    asm volatile(
        "mma.sync.aligned.m16n8k16.row.col.f32.bf16.bf16.f32 "
        "{%0,%1,%2,%3}, {%4,%5,%6,%7}, {%8,%9}, {%0,%1,%2,%3};\n"
        : "+f"(c[0]), "+f"(c[1]), "+f"(c[2]), "+f"(c[3])
        : "r"(a[0]), "r"(a[1]), "r"(a[2]), "r"(a[3]), "r"(b0), "r"(b1));
}

// ---------------------------------------------------------------------------
__global__ void prep_kernel(const float* __restrict__ conv_w,
                            const float* __restrict__ keys)
{
    const int i = blockIdx.x * 256 + threadIdx.x;   // 0..32767
    const int k2 = i >> 8, n = i & 255;
    g_wP[i] = pack_bf16(conv_w[n * HIST + 2 * k2],
                        conv_w[n * HIST + 2 * k2 + 1]);
    if (i < (DIMC / 2) * NPAT) {
        const int d2 = i >> 6, p = i & 63;
        g_keysP[i] = pack_bf16(keys[(2 * d2) * NPAT + p],
                               keys[(2 * d2 + 1) * NPAT + p]);
    }
}

// ---------------------------------------------------------------------------
// Fused kernel: one block per batch, 576 threads (18 warps).
//   warps 0-15 : conv GEMM + scores GEMM (bf16 mma.sync), tile c
//   warp  16   : softmax-EMA recurrence, tile c-1 (scores ring -> e ring)
//   warp  17   : GEMV signal + relu(sig - x) output, tile c-2
// ---------------------------------------------------------------------------
__global__ __launch_bounds__(576, 1)
void fused_kernel(const float* __restrict__ x,
                  const float* __restrict__ avg_scores,
                  const float* __restrict__ conv_b,
                  const float* __restrict__ shapes,
                  float* __restrict__ out)
{
    extern __shared__ char smc[];
    float*    sBias = (float*)(smc + FB_BIAS);
    uint32_t* sxp   = (uint32_t*)(smc + FB_SXP);
    uint32_t* soutp = (uint32_t*)(smc + FB_SOUT);
    float*    sring = (float*)(smc + FB_SRING);
    float*    ering = (float*)(smc + FB_ERING);
    float*    sinv  = (float*)(smc + FB_SINV);

    const int b    = blockIdx.x;
    const int tid  = threadIdx.x;
    const int w    = tid >> 5;
    const int lane = tid & 31;
    const int gid  = lane >> 2;
    const int tig  = lane & 3;
    const float invP = 1.0f / (float)NPAT;

    const float* xr = x + (size_t)b * LSEQ;

    // ---- one-time init ----
    if (tid < 256) sBias[tid] = conv_b[tid];

    float avg0 = 0.0f, avg1 = 0.0f;              // scan state (w16)
    if (w == 16) {
        avg0 = avg_scores[b * NPAT + lane];
        avg1 = avg_scores[b * NPAT + lane + 32];
    }

    uint64_t shp0[NPAT / 2], shp1[NPAT / 2];     // consumer state (w17)
    if (w == 17) {
#pragma unroll
        for (int i = 0; i < NPAT / 2; i++) {
            float a0 = shapes[(2 * i) * WINW + lane];
            float a1 = shapes[(2 * i + 1) * WINW + lane];
            asm("mov.b64 %0, {%1, %2};" : "=l"(shp0[i]) : "f"(a0), "f"(a1));
            float c0 = shapes[(2 * i) * WINW + lane + 32];
            float c1 = shapes[(2 * i + 1) * WINW + lane + 32];
            asm("mov.b64 %0, {%1, %2};" : "=l"(shp1[i]) : "f"(c0), "f"(c1));
        }
    }
    __syncthreads();

    // =================== pipelined main loop ===================
    for (int c = 0; c < NTIL + 2; c++) {
        if (w < 16) {
            // ---------------- GEMM team: tile c ----------------
            if (c < NTIL) {
                const int t0c = c * TT;
                // stage x windows as bf16x2 (swizzled, zero left pad)
                {
                    const int base = t0c * WINW - (HIST - 1);
                    for (int i = tid; i < XWP; i += 512) {
                        const int p0 = base + 2 * i;
                        const float v0 = (p0     >= 0) ? xr[p0]     : 0.0f;
                        const float v1 = (p0 + 1 >= 0) ? xr[p0 + 1] : 0.0f;
                        const int ph = i ^ (((i >> 5) & 7) << 2);
                        sxp[ph] = pack_bf16(v0, v1);
                    }
                }
                asm volatile("bar.sync 1, 512;" ::: "memory");

                // ---- conv GEMM: C[64 x 16] per warp ----
                float acc[4][2][4] = {};
                const int n0w = w * 16;
                uint32_t aw[2][4][4];
                uint32_t wb[2][2][2];

                auto loadA = [&](int kt, uint32_t a[4][4]) {
                    const int j0 = kt * 8;
                    const int v  = (gid + (kt >> 2)) & 7;
                    const int c0 = (j0 + tig)     ^ (v << 2);
                    const int c1 = (j0 + tig + 4) ^ (v << 2);
                    const uint32_t* bp = sxp + gid * 32;
#pragma unroll
                    for (int mt = 0; mt < 4; mt++) {
                        a[mt][0] = bp[mt * 512 + c0];
                        a[mt][1] = bp[mt * 512 + 256 + c0];
                        a[mt][2] = bp[mt * 512 + c1];
                        a[mt][3] = bp[mt * 512 + 256 + c1];
                    }
                };
                auto loadB = [&](int kt, uint32_t wb_[2][2]) {
                    const uint32_t* pb = g_wP + (size_t)(kt * 8 + tig) * 256 + n0w + gid;
                    wb_[0][0] = pb[0];
                    wb_[0][1] = pb[4 * 256];
                    wb_[1][0] = pb[8];
                    wb_[1][1] = pb[4 * 256 + 8];
                };

                loadA(0, aw[0]);
                loadB(0, wb[0]);
#pragma unroll 4
                for (int kt = 0; kt < 16; kt++) {
                    const int cur = kt & 1, nxt = cur ^ 1;
                    if (kt < 15) {
                        loadB(kt + 1, wb[nxt]);
                        loadA(kt + 1, aw[nxt]);
                    }
#pragma unroll
                    for (int nt = 0; nt < 2; nt++) {
#pragma unroll
                        for (int mt = 0; mt < 4; mt++)
                            mma16(acc[mt][nt], aw[cur][mt],
                                  wb[cur][nt][0], wb[cur][nt][1]);
                    }
                }

                // ---- epilogue: bias + relu -> soutp bf16x2 ----
#pragma unroll
                for (int mt = 0; mt < 4; mt++) {
#pragma unroll
                    for (int nt = 0; nt < 2; nt++) {
                        const int col = n0w + nt * 8 + 2 * tig;
                        const float bb0 = sBias[col], bb1 = sBias[col + 1];
                        const int jd = (n0w >> 1) + nt * 4 + tig;
                        const int r0 = mt * 16 + gid;
                        soutp[r0 * SOUTP + jd] =
                            pack_bf16(fmaxf(acc[mt][nt][0] + bb0, 0.0f),
                                      fmaxf(acc[mt][nt][1] + bb1, 0.0f));
                        soutp[(r0 + 8) * SOUTP + jd] =
                            pack_bf16(fmaxf(acc[mt][nt][2] + bb0, 0.0f),
                                      fmaxf(acc[mt][nt][3] + bb1, 0.0f));
                    }
                }
                asm volatile("bar.sync 1, 512;" ::: "memory");

                // ---- scores GEMM: warp = mt x 16-p group ----
                {
                    const int mt = w & 3;
                    const int pg = w >> 2;
                    float sc[2][4] = {};
                    uint32_t af[2][4];
                    uint32_t kf[2][2][2];

                    auto loadA2 = [&](int kt, uint32_t a[4]) {
                        const uint32_t* pA = soutp + (mt * 16 + gid) * SOUTP
                                             + kt * 8 + tig;
                        a[0] = pA[0];
                        a[1] = pA[8 * SOUTP];
                        a[2] = pA[4];
                        a[3] = pA[8 * SOUTP + 4];
                    };
                    auto loadK = [&](int kt, uint32_t kf_[2][2]) {
                        const uint32_t* pk = g_keysP + (size_t)(kt * 8 + tig) * 64
                                             + pg * 16 + gid;
                        kf_[0][0] = pk[0];
                        kf_[0][1] = pk[4 * 64];
                        kf_[1][0] = pk[8];
                        kf_[1][1] = pk[4 * 64 + 8];
                    };

                    loadA2(0, af[0]);
                    loadK(0, kf[0]);
#pragma unroll 4
                    for (int kt = 0; kt < 16; kt++) {
                        const int cur = kt & 1, nxt = cur ^ 1;
                        if (kt < 15) {
                            loadK(kt + 1, kf[nxt]);
                            loadA2(kt + 1, af[nxt]);
                        }
                        mma16(sc[0], af[cur], kf[cur][0][0], kf[cur][0][1]);
                        mma16(sc[1], af[cur], kf[cur][1][0], kf[cur][1][1]);
                    }

                    // relu6 -> scores ring (smem)
                    float* sr = sring + (c & 1) * (TT * NPAT);
#pragma unroll
                    for (int nt = 0; nt < 2; nt++) {
                        const int p  = pg * 16 + nt * 8 + 2 * tig;
                        const int r0 = mt * 16 + gid;
                        float2 u0 = make_float2(fminf(fmaxf(sc[nt][0], 0.0f), 6.0f),
                                                fminf(fmaxf(sc[nt][1], 0.0f), 6.0f));
                        float2 u1 = make_float2(fminf(fmaxf(sc[nt][2], 0.0f), 6.0f),
                                                fminf(fmaxf(sc[nt][3], 0.0f), 6.0f));
                        *reinterpret_cast<float2*>(&sr[r0 * NPAT + p])       = u0;
                        *reinterpret_cast<float2*>(&sr[(r0 + 8) * NPAT + p]) = u1;
                    }
                }
            }
        } else if (w == 16) {
            // ---------------- scan: tile c-1 ----------------
            if (c >= 1 && c <= NTIL) {
                const int ct = c - 1;
                const float* sc = sring + (ct & 1) * (TT * NPAT);
                float*       eb = ering + (ct & 1) * (TT * NPAT);
                float*       iv = sinv  + (ct & 1) * TT;
#pragma unroll 4
                for (int tt = 0; tt < TT; tt++) {
                    const float s0 = sc[tt * NPAT + lane];
                    const float s1 = sc[tt * NPAT + lane + 32];
                    const float e0 = __expf(s0 - avg0);
                    const float e1 = __expf(s1 - avg1);
                    eb[tt * NPAT + lane]      = e0;
                    eb[tt * NPAT + lane + 32] = e1;
                    float sum = e0 + e1;
#pragma unroll
                    for (int o = 16; o > 0; o >>= 1)
                        sum += __shfl_xor_sync(0xFFFFFFFFu, sum, o);
                    const float inv = __fdividef(1.0f, sum);
                    if (lane == 0) iv[tt] = inv;
                    const float a0p = avg0 - invP;
                    const float a1p = avg1 - invP;
                    avg0 = fmaf(e0, inv, a0p);
                    avg1 = fmaf(e1, inv, a1p);
                }
            }
        } else {
            // ---------------- consumer: tile c-2 ----------------
            if (c >= 2) {
                const int ct = c - 2;
                const float* eb = ering + (ct & 1) * (TT * NPAT);
                const float* iv = sinv  + (ct & 1) * TT;
                const float* xt = xr + (size_t)ct * (TT * WINW);
                float* orow = out + (size_t)b * LSEQ + (size_t)ct * (TT * WINW);

                float c0 = xt[lane],          c1 = xt[lane + 32];
                float n0 = xt[WINW + lane],   n1 = xt[WINW + lane + 32];
#pragma unroll 2
                for (int tt = 0; tt < TT; tt++) {
                    float f0 = 0.0f, f1 = 0.0f;
                    if (tt + 2 < TT) {
                        f0 = xt[(tt + 2) * WINW + lane];
                        f1 = xt[(tt + 2) * WINW + lane + 32];
                    }
                    const uint64_t* ep =
                        reinterpret_cast<const uint64_t*>(eb + tt * NPAT);
                    const float inv = iv[tt];
                    uint64_t a0a = 0ull, a0b = 0ull, a1a = 0ull, a1b = 0ull;
#pragma unroll
                    for (int i = 0; i < 16; i++) {
                        const uint64_t ev = ep[i];
                        asm("fma.rn.f32x2 %0, %1, %2, %0;"
                            : "+l"(a0a) : "l"(ev), "l"(shp0[i]));
                        asm("fma.rn.f32x2 %0, %1, %2, %0;"
                            : "+l"(a1a) : "l"(ev), "l"(shp1[i]));
                    }
#pragma unroll
                    for (int i = 16; i < 32; i++) {
                        const uint64_t ev = ep[i];
                        asm("fma.rn.f32x2 %0, %1, %2, %0;"
                            : "+l"(a0b) : "l"(ev), "l"(shp0[i]));
                        asm("fma.rn.f32x2 %0, %1, %2, %0;"
                            : "+l"(a1b) : "l"(ev), "l"(shp1[i]));
                    }
                    float l0, h0, l1, h1, l2, h2, l3, h3;
                    asm("mov.b64 {%0, %1}, %2;" : "=f"(l0), "=f"(h0) : "l"(a0a));
                    asm("mov.b64 {%0, %1}, %2;" : "=f"(l1), "=f"(h1) : "l"(a0b));
                    asm("mov.b64 {%0, %1}, %2;" : "=f"(l2), "=f"(h2) : "l"(a1a));
                    asm("mov.b64 {%0, %1}, %2;" : "=f"(l3), "=f"(h3) : "l"(a1b));
                    const float sig0 = ((l0 + h0) + (l1 + h1)) * inv;
                    const float sig1 = ((l2 + h2) + (l3 + h3)) * inv;

                    orow[tt * WINW + lane]      = fmaxf(sig0 - c0, 0.0f);
                    orow[tt * WINW + lane + 32] = fmaxf(sig1 - c1, 0.0f);
                    c0 = n0; c1 = n1; n0 = f0; n1 = f1;
                }
            }
        }
        __syncthreads();
    }
}

// ---------------------------------------------------------------------------
extern "C" void kernel_launch(void* const* d_in, const int* in_sizes, int n_in,
                              void* d_out, int out_size)
{
    const float* x          = (const float*)d_in[0];
    const float* avg_scores = (const float*)d_in[1];
    const float* conv_w     = (const float*)d_in[2];
    const float* conv_b     = (const float*)d_in[3];
    const float* keys       = (const float*)d_in[4];
    const float* shapes     = (const float*)d_in[5];
    float* out = (float*)d_out;

    cudaFuncSetAttribute(fused_kernel,
                         cudaFuncAttributeMaxDynamicSharedMemorySize,
                         FUSED_SMEM);

    prep_kernel<<<128, 256>>>(conv_w, keys);
    fused_kernel<<<BSZ, 576, FUSED_SMEM>>>(x, avg_scores, conv_b, shapes, out);
}

// round 16
// speedup vs baseline: 1.2346x; 1.2346x over previous
#include <cuda_runtime.h>
#include <cuda_bf16.h>
#include <cstdint>

// Problem constants
#define BSZ   256
#define LSEQ  65536
#define HIST  256
#define WINW  64
#define DIMC  256
#define NPAT  64
#define TSTEP 1024

// Batch grouping for k1/scan overlap
#define NGRP  4
#define GB    (BSZ / NGRP)           // 64 batches per group

// Kernel-1 tiling
#define TT    64                     // t rows per block
#define XWIN  ((TT-1)*WINW + HIST)   // 4288 x elements per block
#define XWP   (XWIN/2)               // 2144 bf16x2 pairs
#define SOUTP 132                    // souts row stride (uints)

// smem layout (uints) for kernel 1
#define OFF_SX    0
#define OFF_OUT   2176
#define OFF_BIAS  (OFF_OUT + 64*SOUTP)
#define K1_SMEM_UINTS (OFF_BIAS + 256)
#define K1_SMEM_BYTES (K1_SMEM_UINTS * 4)

// Kernel-2 chunking
#define SCCH  32
#define SNCH  (TSTEP / SCCH)

// Scratch
__device__ float    g_scores[BSZ * TSTEP * NPAT];   // 64 MiB
__device__ uint32_t g_wP[(HIST/2) * DIMC];          // W^T bf16x2: [k2][n]
__device__ uint32_t g_keysP[(DIMC/2) * NPAT];       // keys bf16x2: [d2][p]

// ---------------------------------------------------------------------------
__device__ __forceinline__ uint32_t pack_bf16(float lo, float hi) {
    uint32_t r;
    asm("cvt.rn.bf16x2.f32 %0, %1, %2;" : "=r"(r) : "f"(hi), "f"(lo));
    return r;
}

// D += A(16x16 bf16, row) * B(16x8 bf16, col), fp32 accum
__device__ __forceinline__ void mma16(float c[4], const uint32_t a[4],
                                      uint32_t b0, uint32_t b1) {
    asm volatile(
        "mma.sync.aligned.m16n8k16.row.col.f32.bf16.bf16.f32 "
        "{%0,%1,%2,%3}, {%4,%5,%6,%7}, {%8,%9}, {%0,%1,%2,%3};\n"
        : "+f"(c[0]), "+f"(c[1]), "+f"(c[2]), "+f"(c[3])
        : "r"(a[0]), "r"(a[1]), "r"(a[2]), "r"(a[3]), "r"(b0), "r"(b1));
}

// ---------------------------------------------------------------------------
__global__ void prep_kernel(const float* __restrict__ conv_w,
                            const float* __restrict__ keys)
{
    const int i = blockIdx.x * 256 + threadIdx.x;   // 0..32767
    const int k2 = i >> 8, n = i & 255;
    g_wP[i] = pack_bf16(conv_w[n * HIST + 2 * k2],
                        conv_w[n * HIST + 2 * k2 + 1]);
    if (i < (DIMC / 2) * NPAT) {
        const int d2 = i >> 6, p = i & 63;
        g_keysP[i] = pack_bf16(keys[(2 * d2) * NPAT + p],
                               keys[(2 * d2 + 1) * NPAT + p]);
    }
}

// ---------------------------------------------------------------------------
// Kernel 1 (R11-proven): conv-as-GEMM (bf16 m16n8k16) + relu + scores GEMM
// + relu6. 512 threads; blockIdx.x = batch within group (b0 offset).
// ---------------------------------------------------------------------------
__global__ __launch_bounds__(512, 1)
void conv_scores_mma(const float* __restrict__ x,
                     const float* __restrict__ conv_b,
                     int b0)
{
    extern __shared__ uint32_t smu[];
    uint32_t* sxp   = smu + OFF_SX;
    uint32_t* soutp = smu + OFF_OUT;
    float*    sBias = (float*)(smu + OFF_BIAS);

    const int b    = b0 + blockIdx.x;
    const int t0   = blockIdx.y * TT;
    const int tid  = threadIdx.x;
    const int w    = tid >> 5;
    const int lane = tid & 31;
    const int gid  = lane >> 2;
    const int tig  = lane & 3;

    // ---- stage compact x as bf16x2 pairs (swizzled, zero left pad) ----
    {
        const float* xr = x + (size_t)b * LSEQ;
        const int base = t0 * WINW - (HIST - 1);
        for (int i = tid; i < XWP; i += 512) {
            const int p0 = base + 2 * i;
            const float v0 = (p0     >= 0) ? xr[p0]     : 0.0f;
            const float v1 = (p0 + 1 >= 0) ? xr[p0 + 1] : 0.0f;
            const int ph = i ^ (((i >> 5) & 7) << 2);
            sxp[ph] = pack_bf16(v0, v1);
        }
    }
    if (tid < 256) sBias[tid] = conv_b[tid];
    __syncthreads();

    // ================= conv GEMM: C[64 x 16] per warp =================
    float acc[4][2][4] = {};
    const int n0w = w * 16;

    uint32_t aw[2][4][4];
    uint32_t wb[2][2][2];

    auto loadA = [&](int kt, uint32_t a[4][4]) {
        const int j0 = kt * 8;
        const int v  = (gid + (kt >> 2)) & 7;
        const int c0 = (j0 + tig)     ^ (v << 2);
        const int c1 = (j0 + tig + 4) ^ (v << 2);
        const uint32_t* bp = sxp + gid * 32;
#pragma unroll
        for (int mt = 0; mt < 4; mt++) {
            a[mt][0] = bp[mt * 512 + c0];
            a[mt][1] = bp[mt * 512 + 256 + c0];
            a[mt][2] = bp[mt * 512 + c1];
            a[mt][3] = bp[mt * 512 + 256 + c1];
        }
    };
    auto loadB = [&](int kt, uint32_t wb_[2][2]) {
        const uint32_t* pb = g_wP + (size_t)(kt * 8 + tig) * 256 + n0w + gid;
        wb_[0][0] = pb[0];
        wb_[0][1] = pb[4 * 256];
        wb_[1][0] = pb[8];
        wb_[1][1] = pb[4 * 256 + 8];
    };

    loadA(0, aw[0]);
    loadB(0, wb[0]);

#pragma unroll 4
    for (int kt = 0; kt < 16; kt++) {
        const int cur = kt & 1, nxt = cur ^ 1;
        if (kt < 15) {
            loadB(kt + 1, wb[nxt]);
            loadA(kt + 1, aw[nxt]);
        }
#pragma unroll
        for (int nt = 0; nt < 2; nt++) {
#pragma unroll
            for (int mt = 0; mt < 4; mt++)
                mma16(acc[mt][nt], aw[cur][mt], wb[cur][nt][0], wb[cur][nt][1]);
        }
    }

    // ---- epilogue: bias + relu -> bf16x2 pairs (along d) in soutp ----
#pragma unroll
    for (int mt = 0; mt < 4; mt++) {
#pragma unroll
        for (int nt = 0; nt < 2; nt++) {
            const int col = n0w + nt * 8 + 2 * tig;
            const float bb0 = sBias[col], bb1 = sBias[col + 1];
            const int jd = (n0w >> 1) + nt * 4 + tig;
            const int r0 = mt * 16 + gid;
            soutp[r0 * SOUTP + jd] =
                pack_bf16(fmaxf(acc[mt][nt][0] + bb0, 0.0f),
                          fmaxf(acc[mt][nt][1] + bb1, 0.0f));
            soutp[(r0 + 8) * SOUTP + jd] =
                pack_bf16(fmaxf(acc[mt][nt][2] + bb0, 0.0f),
                          fmaxf(acc[mt][nt][3] + bb1, 0.0f));
        }
    }
    __syncthreads();

    // ================= scores GEMM: warp = mt x 16-p group =================
    {
        const int mt = w & 3;
        const int pg = w >> 2;
        float sc[2][4] = {};

        uint32_t af[2][4];
        uint32_t kf[2][2][2];

        auto loadA2 = [&](int kt, uint32_t a[4]) {
            const uint32_t* pA = soutp + (mt * 16 + gid) * SOUTP + kt * 8 + tig;
            a[0] = pA[0];
            a[1] = pA[8 * SOUTP];
            a[2] = pA[4];
            a[3] = pA[8 * SOUTP + 4];
        };
        auto loadK = [&](int kt, uint32_t kf_[2][2]) {
            const uint32_t* pk = g_keysP + (size_t)(kt * 8 + tig) * 64
                                 + pg * 16 + gid;
            kf_[0][0] = pk[0];
            kf_[0][1] = pk[4 * 64];
            kf_[1][0] = pk[8];
            kf_[1][1] = pk[4 * 64 + 8];
        };

        loadA2(0, af[0]);
        loadK(0, kf[0]);

#pragma unroll 4
        for (int kt = 0; kt < 16; kt++) {
            const int cur = kt & 1, nxt = cur ^ 1;
            if (kt < 15) {
                loadK(kt + 1, kf[nxt]);
                loadA2(kt + 1, af[nxt]);
            }
            mma16(sc[0], af[cur], kf[cur][0][0], kf[cur][0][1]);
            mma16(sc[1], af[cur], kf[cur][1][0], kf[cur][1][1]);
        }

        // relu6 -> g_scores[b][t][p]
        float* gs = g_scores + ((size_t)b * TSTEP + t0) * NPAT;
#pragma unroll
        for (int nt = 0; nt < 2; nt++) {
            const int p  = pg * 16 + nt * 8 + 2 * tig;
            const int r0 = mt * 16 + gid;
            float2 u0 = make_float2(fminf(fmaxf(sc[nt][0], 0.0f), 6.0f),
                                    fminf(fmaxf(sc[nt][1], 0.0f), 6.0f));
            float2 u1 = make_float2(fminf(fmaxf(sc[nt][2], 0.0f), 6.0f),
                                    fminf(fmaxf(sc[nt][3], 0.0f), 6.0f));
            *reinterpret_cast<float2*>(&gs[r0 * NPAT + p])       = u0;
            *reinterpret_cast<float2*>(&gs[(r0 + 8) * NPAT + p]) = u1;
        }
    }
}

// ---------------------------------------------------------------------------
// Kernel 2 (R11-proven): 2 batches per block; warps 0/1 producers,
// warps 2-4 / 5-7 consumers. b0 = batch offset of this group.
// ---------------------------------------------------------------------------
__global__ __launch_bounds__(256)
void scan_signal_kernel(const float* __restrict__ avg_scores,
                        const float* __restrict__ shapes,
                        const float* __restrict__ x,
                        float* __restrict__ out,
                        int b0)
{
    extern __shared__ float ds[];
    float* ring = ds;              // [2 batch][2 buf][SCCH][NPAT] = 8192 f
    float* rinv = ds + 8192;       // [2][2][SCCH] = 128 f
    float* sxb  = ds + 8320;       // [2][SCCH*WINW] = 4096 f

    const int tid  = threadIdx.x;
    const int w    = tid >> 5;
    const int lane = tid & 31;
    const float invP = 1.0f / (float)NPAT;

    // ---- producer state (w<2) ----
    float avg0 = 0.0f, avg1 = 0.0f;
    float pf0[8], pf1[8];
    const float* srow = nullptr;
    if (w < 2) {
        const int b = b0 + blockIdx.x * 2 + w;
        srow = g_scores + (size_t)b * TSTEP * NPAT;
        avg0 = avg_scores[b * NPAT + lane];
        avg1 = avg_scores[b * NPAT + lane + 32];
#pragma unroll
        for (int j = 0; j < 8; j++) {
            pf0[j] = srow[j * NPAT + lane];
            pf1[j] = srow[j * NPAT + lane + 32];
        }
    }

    // ---- consumer state (w>=2) ----
    uint64_t shp0[NPAT / 2], shp1[NPAT / 2];
    int g = 0, cw = 0, bc = 0;
    if (w >= 2) {
        g  = (w - 2) / 3;
        cw = (w - 2) - 3 * g;
        bc = b0 + blockIdx.x * 2 + g;
#pragma unroll
        for (int i = 0; i < NPAT / 2; i++) {
            float a0 = shapes[(2 * i) * WINW + lane];
            float a1 = shapes[(2 * i + 1) * WINW + lane];
            asm("mov.b64 %0, {%1, %2};" : "=l"(shp0[i]) : "f"(a0), "f"(a1));
            float c0 = shapes[(2 * i) * WINW + lane + 32];
            float c1 = shapes[(2 * i + 1) * WINW + lane + 32];
            asm("mov.b64 %0, {%1, %2};" : "=l"(shp1[i]) : "f"(c0), "f"(c1));
        }
    }

    for (int c = 0; c <= SNCH; c++) {
        if (w < 2) {
            if (c < SNCH) {
                float* buf = ring + (size_t)(w * 2 + (c & 1)) * SCCH * NPAT;
                float* biv = rinv + (w * 2 + (c & 1)) * SCCH;
#pragma unroll 1
                for (int u = 0; u < SCCH; u += 8) {
#pragma unroll
                    for (int j = 0; j < 8; j++) {
                        const int tt = u + j;
                        const int t  = c * SCCH + tt;
                        const float s0 = pf0[j];
                        const float s1 = pf1[j];
                        const int tn = t + 8;
                        if (tn < TSTEP) {
                            pf0[j] = srow[tn * NPAT + lane];
                            pf1[j] = srow[tn * NPAT + lane + 32];
                        }
                        const float e0 = __expf(s0 - avg0);
                        const float e1 = __expf(s1 - avg1);
                        buf[tt * NPAT + lane]      = e0;
                        buf[tt * NPAT + lane + 32] = e1;
                        float sum = e0 + e1;
#pragma unroll
                        for (int o = 16; o > 0; o >>= 1)
                            sum += __shfl_xor_sync(0xFFFFFFFFu, sum, o);
                        const float inv = __fdividef(1.0f, sum);
                        if (lane == 0) biv[tt] = inv;
                        const float a0p = avg0 - invP;
                        const float a1p = avg1 - invP;
                        avg0 = fmaf(e0, inv, a0p);
                        avg1 = fmaf(e1, inv, a1p);
                    }
                }
            }
        } else {
            if (c > 0) {
                const int cc = c - 1;
                const float* buf = ring + (size_t)(g * 2 + (cc & 1)) * SCCH * NPAT;
                const float* biv = rinv + (g * 2 + (cc & 1)) * SCCH;
                float* sx = sxb + g * (SCCH * WINW);

                const float4* xc = reinterpret_cast<const float4*>(
                    x + (size_t)bc * LSEQ + (size_t)cc * SCCH * WINW);
                float4* sx4 = reinterpret_cast<float4*>(sx);
                for (int i = cw * 32 + lane; i < SCCH * WINW / 4; i += 96)
                    sx4[i] = xc[i];
                if (g == 0) asm volatile("bar.sync 1, 96;" ::: "memory");
                else        asm volatile("bar.sync 2, 96;" ::: "memory");

                float* orow = out + (size_t)bc * LSEQ;
                for (int tt = cw; tt < SCCH; tt += 3) {
                    const uint64_t* ep =
                        reinterpret_cast<const uint64_t*>(buf + tt * NPAT);
                    const float inv = biv[tt];
                    uint64_t acc0 = 0ull, acc1 = 0ull;
#pragma unroll
                    for (int i = 0; i < NPAT / 2; i++) {
                        const uint64_t ev = ep[i];
                        asm("fma.rn.f32x2 %0, %1, %2, %0;"
                            : "+l"(acc0) : "l"(ev), "l"(shp0[i]));
                        asm("fma.rn.f32x2 %0, %1, %2, %0;"
                            : "+l"(acc1) : "l"(ev), "l"(shp1[i]));
                    }
                    float l0, h0, l1, h1;
                    asm("mov.b64 {%0, %1}, %2;" : "=f"(l0), "=f"(h0) : "l"(acc0));
                    asm("mov.b64 {%0, %1}, %2;" : "=f"(l1), "=f"(h1) : "l"(acc1));
                    const float sig0 = (l0 + h0) * inv;
                    const float sig1 = (l1 + h1) * inv;

                    const float xa = sx[tt * WINW + lane];
                    const float xb = sx[tt * WINW + lane + 32];
                    const int o0 = (cc * SCCH + tt) * WINW + lane;
                    orow[o0]      = fmaxf(sig0 - xa, 0.0f);
                    orow[o0 + 32] = fmaxf(sig1 - xb, 0.0f);
                }
            }
        }
        __syncthreads();
    }
}

// ---------------------------------------------------------------------------
// Launch: fork-join overlap. k1 group g completes -> event -> side stream
// runs scan(g) while main stream runs k1(g+1). Falls back to serial (=R11)
// if stream/event creation is unavailable.
// ---------------------------------------------------------------------------
extern "C" void kernel_launch(void* const* d_in, const int* in_sizes, int n_in,
                              void* d_out, int out_size)
{
    const float* x          = (const float*)d_in[0];
    const float* avg_scores = (const float*)d_in[1];
    const float* conv_w     = (const float*)d_in[2];
    const float* conv_b     = (const float*)d_in[3];
    const float* keys       = (const float*)d_in[4];
    const float* shapes     = (const float*)d_in[5];
    float* out = (float*)d_out;

    cudaFuncSetAttribute(conv_scores_mma,
                         cudaFuncAttributeMaxDynamicSharedMemorySize,
                         K1_SMEM_BYTES);
    const int scan_smem = (8192 + 128 + 4096) * 4;
    cudaFuncSetAttribute(scan_signal_kernel,
                         cudaFuncAttributeMaxDynamicSharedMemorySize,
                         scan_smem);

    cudaStream_t s2 = nullptr;
    cudaEvent_t evK[NGRP], evJ = nullptr;
    bool overlap = (cudaStreamCreateWithFlags(&s2, cudaStreamNonBlocking)
                    == cudaSuccess);
    if (overlap) {
        for (int g = 0; g < NGRP && overlap; g++)
            overlap = (cudaEventCreateWithFlags(&evK[g],
                       cudaEventDisableTiming) == cudaSuccess);
        if (overlap)
            overlap = (cudaEventCreateWithFlags(&evJ,
                       cudaEventDisableTiming) == cudaSuccess);
    }

    prep_kernel<<<128, 256>>>(conv_w, keys);

    if (overlap) {
        for (int g = 0; g < NGRP; g++) {
            dim3 grid1(GB, TSTEP / TT);
            conv_scores_mma<<<grid1, 512, K1_SMEM_BYTES>>>(x, conv_b, g * GB);
            cudaEventRecord(evK[g], 0);
            cudaStreamWaitEvent(s2, evK[g], 0);
            scan_signal_kernel<<<GB / 2, 256, scan_smem, s2>>>(
                avg_scores, shapes, x, out, g * GB);
        }
        cudaEventRecord(evJ, s2);
        cudaStreamWaitEvent(0, evJ, 0);
    } else {
        // serial fallback (identical work/order, no overlap)
        for (int g = 0; g < NGRP; g++) {
            dim3 grid1(GB, TSTEP / TT);
            conv_scores_mma<<<grid1, 512, K1_SMEM_BYTES>>>(x, conv_b, g * GB);
        }
        for (int g = 0; g < NGRP; g++)
            scan_signal_kernel<<<GB / 2, 256, scan_smem>>>(
                avg_scores, shapes, x, out, g * GB);
    }
}